// round 1
// baseline (speedup 1.0000x reference)
#include <cuda_runtime.h>
#include <cstdint>

// Problem constants
#define SLATE   5
#define DDIM    20
#define KSEL    100
#define MAXN    2000000
#define NBINS   2048          // top-11-bit radix histogram
#define CAP     65536         // per-row candidate cap after coarse threshold
#define SH_CAP  6000          // 64-bit entries in shared for final select (48KB)

// -------- device scratch (allocation-free: module globals) --------
__device__ float              g_proto[128];          // 100 used
__device__ float              g_pn2[8];
__device__ unsigned           g_keys[(size_t)SLATE * MAXN];     // 40 MB
__device__ unsigned           g_hist[SLATE * NBINS];
__device__ unsigned           g_keyLimit[8];
__device__ unsigned           g_candCount[8];
__device__ unsigned long long g_cand[(size_t)SLATE * CAP];      // 2.5 MB

__device__ __forceinline__ float leaky(float x) { return x > 0.0f ? x : 0.01f * x; }

// monotone float->uint key (ascending float => ascending uint)
__device__ __forceinline__ unsigned fkey(float f) {
    unsigned u = __float_as_uint(f);
    return (u & 0x80000000u) ? ~u : (u | 0x80000000u);
}

// -------- kernel 0: zero per-launch scratch --------
__global__ void init_kernel() {
    int t = blockIdx.x * blockDim.x + threadIdx.x;
    for (int i = t; i < SLATE * NBINS; i += gridDim.x * blockDim.x) g_hist[i] = 0;
    if (t < 8) g_candCount[t] = 0;
}

// -------- kernel 1: MLP 20->256->512->100 (leaky relu each layer) --------
__global__ __launch_bounds__(512) void mlp_kernel(
    const float* __restrict__ x_in,
    const float* __restrict__ W0, const float* __restrict__ b0,
    const float* __restrict__ W1, const float* __restrict__ b1,
    const float* __restrict__ W2, const float* __restrict__ b2)
{
    __shared__ float x[DDIM];
    __shared__ float h0[256];
    __shared__ float h1[512];
    __shared__ float pr[100];
    int tid = threadIdx.x;

    if (tid < DDIM) x[tid] = x_in[tid];
    __syncthreads();

    if (tid < 256) {
        float acc = b0[tid];
        #pragma unroll
        for (int k = 0; k < DDIM; k++) acc = fmaf(x[k], W0[k * 256 + tid], acc);
        h0[tid] = leaky(acc);
    }
    __syncthreads();

    {
        float acc = b1[tid];
        #pragma unroll 8
        for (int k = 0; k < 256; k++) acc = fmaf(h0[k], W1[k * 512 + tid], acc);
        h1[tid] = leaky(acc);
    }
    __syncthreads();

    if (tid < 100) {
        float acc = b2[tid];
        #pragma unroll 8
        for (int k = 0; k < 512; k++) acc = fmaf(h1[k], W2[k * 100 + tid], acc);
        float v = leaky(acc);
        pr[tid] = v;
        g_proto[tid] = v;
    }
    __syncthreads();

    if (tid < SLATE) {
        float s = 0.0f;
        #pragma unroll
        for (int d = 0; d < DDIM; d++) { float v = pr[tid * DDIM + d]; s = fmaf(v, v, s); }
        g_pn2[tid] = s;
    }
}

// -------- kernel 2: score all docs, store keys, build MSB histogram --------
__global__ __launch_bounds__(512) void score_kernel(const float* __restrict__ docs, int N)
{
    __shared__ unsigned shist[SLATE * NBINS];   // 40 KB
    __shared__ float sp[100];
    __shared__ float spn[SLATE];
    int tid = threadIdx.x;

    for (int t = tid; t < SLATE * NBINS; t += blockDim.x) shist[t] = 0;
    if (tid < 100) sp[tid] = g_proto[tid];
    if (tid < SLATE) spn[tid] = g_pn2[tid];
    __syncthreads();

    const float4* d4 = (const float4*)docs;   // 20 floats = 5 x float4 per row
    for (int i = blockIdx.x * blockDim.x + tid; i < N; i += gridDim.x * blockDim.x) {
        size_t base = (size_t)i * 5;
        float4 v0 = d4[base + 0], v1 = d4[base + 1], v2 = d4[base + 2],
               v3 = d4[base + 3], v4 = d4[base + 4];
        float vv[20] = { v0.x, v0.y, v0.z, v0.w,  v1.x, v1.y, v1.z, v1.w,
                         v2.x, v2.y, v2.z, v2.w,  v3.x, v3.y, v3.z, v3.w,
                         v4.x, v4.y, v4.z, v4.w };
        float cn2 = 0.0f;
        #pragma unroll
        for (int k = 0; k < DDIM; k++) cn2 = fmaf(vv[k], vv[k], cn2);

        #pragma unroll
        for (int j = 0; j < SLATE; j++) {
            float dot = 0.0f;
            #pragma unroll
            for (int k = 0; k < DDIM; k++) dot = fmaf(sp[j * DDIM + k], vv[k], dot);
            float d2 = cn2 - 2.0f * dot + spn[j];
            unsigned key = fkey(d2);
            g_keys[(size_t)j * N + i] = key;
            unsigned bin = key >> 21;
            // warp-aggregated histogram: bulk bins would serialize shared atomics
            unsigned am = __activemask();
            unsigned m  = __match_any_sync(am, bin);
            int leader  = __ffs(m) - 1;
            if ((int)(threadIdx.x & 31) == leader)
                atomicAdd(&shist[j * NBINS + bin], (unsigned)__popc(m));
        }
    }
    __syncthreads();
    for (int t = tid; t < SLATE * NBINS; t += blockDim.x) {
        unsigned c = shist[t];
        if (c) atomicAdd(&g_hist[t], c);
    }
}

// -------- kernel 3: per-row scan, find key limit of the K-th smallest --------
__global__ void scan_kernel() {
    int r = threadIdx.x;
    if (r < SLATE) {
        unsigned c = 0;
        unsigned b = 0;
        for (b = 0; b < NBINS; b++) {
            c += g_hist[r * NBINS + b];
            if (c >= KSEL) break;
        }
        g_keyLimit[r] = (b >= NBINS - 1) ? 0xFFFFFFFFu : ((b + 1u) << 21);
    }
}

// -------- kernel 4: compact candidates below limit --------
__global__ __launch_bounds__(512) void collect_kernel(int N)
{
    __shared__ unsigned lim[SLATE];
    if (threadIdx.x < SLATE) lim[threadIdx.x] = g_keyLimit[threadIdx.x];
    __syncthreads();

    for (int i = blockIdx.x * blockDim.x + threadIdx.x; i < N;
         i += gridDim.x * blockDim.x) {
        #pragma unroll
        for (int j = 0; j < SLATE; j++) {
            unsigned key = g_keys[(size_t)j * N + i];
            if (key < lim[j]) {
                unsigned pos = atomicAdd(&g_candCount[j], 1u);
                if (pos < CAP)
                    g_cand[(size_t)j * CAP + pos] =
                        ((unsigned long long)key << 32) | (unsigned)i;
            }
        }
    }
}

// -------- kernel 5: exact rank among candidates, gather output --------
// Packed (key<<32)|idx compares exactly like jax top_k ordering:
// ascending d2, ties broken by lower index.
__global__ __launch_bounds__(1024) void select_kernel(
    const float* __restrict__ docs, float* __restrict__ out, int out_size)
{
    extern __shared__ unsigned long long sh[];
    int j = blockIdx.x;
    int n = (int)min(g_candCount[j], (unsigned)CAP);
    int nsh = n < SH_CAP ? n : SH_CAP;

    for (int t = threadIdx.x; t < nsh; t += blockDim.x)
        sh[t] = g_cand[(size_t)j * CAP + t];
    __syncthreads();

    for (int t = threadIdx.x; t < n; t += blockDim.x) {
        unsigned long long my = (t < nsh) ? sh[t] : g_cand[(size_t)j * CAP + t];
        int rank = 0;
        for (int s = 0; s < nsh; s++) rank += (sh[s] < my);
        for (int s = nsh; s < n; s++) rank += (g_cand[(size_t)j * CAP + s] < my);

        if (rank < KSEL) {
            unsigned di  = (unsigned)(my & 0xFFFFFFFFu);
            int orow     = j * KSEL + rank;
            if (out_size >= SLATE * KSEL * DDIM) {
                const float4* s4 = (const float4*)(docs + (size_t)di * DDIM);
                float4* o4 = (float4*)(out + (size_t)orow * DDIM);
                #pragma unroll
                for (int k = 0; k < 5; k++) o4[k] = s4[k];
                if (out_size >= SLATE * KSEL * DDIM + SLATE * KSEL)
                    out[SLATE * KSEL * DDIM + orow] = (float)di;
            } else {
                // indices-only output layout
                out[orow] = (float)di;
            }
        }
    }
}

extern "C" void kernel_launch(void* const* d_in, const int* in_sizes, int n_in,
                              void* d_out, int out_size)
{
    const float* state = (const float*)d_in[0];
    const float* docs  = (const float*)d_in[1];
    const float* W0    = (const float*)d_in[2];
    const float* b0    = (const float*)d_in[3];
    const float* W1    = (const float*)d_in[4];
    const float* b1    = (const float*)d_in[5];
    const float* W2    = (const float*)d_in[6];
    const float* b2    = (const float*)d_in[7];
    float* out = (float*)d_out;

    int N = in_sizes[1] / DDIM;
    if (N > MAXN) N = MAXN;

    const int threads = 512;
    int blocks = (N + threads * 4 - 1) / (threads * 4);
    if (blocks > 2048) blocks = 2048;
    if (blocks < 1) blocks = 1;

    init_kernel<<<1, 1024>>>();
    mlp_kernel<<<1, 512>>>(state, W0, b0, W1, b1, W2, b2);
    score_kernel<<<blocks, threads>>>(docs, N);
    scan_kernel<<<1, 32>>>();
    collect_kernel<<<blocks, threads>>>(N);
    select_kernel<<<SLATE, 1024, SH_CAP * sizeof(unsigned long long)>>>(docs, out, out_size);
}

// round 2
// speedup vs baseline: 1.6587x; 1.6587x over previous
#include <cuda_runtime.h>
#include <cstdint>

// Problem constants
#define SLATE   5
#define DDIM    20
#define KSEL    100
#define MAXN    2000000
#define NBINS   2048          // top-11-bit radix histogram
#define CAP     65536         // per-row candidate cap after coarse threshold
#define SH_CAP  6000          // 64-bit entries in shared for final select (48KB)

// -------- device scratch (allocation-free: module globals) --------
__device__ float              g_proto[128];          // 100 used
__device__ float              g_pn2[8];
__device__ unsigned           g_keys[(size_t)SLATE * MAXN];     // 40 MB
__device__ unsigned           g_hist[SLATE * NBINS];
__device__ unsigned           g_keyLimit[8];
__device__ unsigned           g_candCount[8];
__device__ unsigned long long g_cand[(size_t)SLATE * CAP];      // 2.5 MB

__device__ __forceinline__ float leaky(float x) { return x > 0.0f ? x : 0.01f * x; }

// monotone float->uint key (ascending float => ascending uint)
__device__ __forceinline__ unsigned fkey(float f) {
    unsigned u = __float_as_uint(f);
    return (u & 0x80000000u) ? ~u : (u | 0x80000000u);
}

// -------- kernel 0: zero per-launch scratch --------
__global__ void init_kernel() {
    int t = blockIdx.x * blockDim.x + threadIdx.x;
    for (int i = t; i < SLATE * NBINS; i += gridDim.x * blockDim.x) g_hist[i] = 0;
    if (t < 8) g_candCount[t] = 0;
}

// -------- kernel 1: MLP 20->256->512->100 (leaky relu each layer) --------
__global__ __launch_bounds__(512) void mlp_kernel(
    const float* __restrict__ x_in,
    const float* __restrict__ W0, const float* __restrict__ b0,
    const float* __restrict__ W1, const float* __restrict__ b1,
    const float* __restrict__ W2, const float* __restrict__ b2)
{
    __shared__ float x[DDIM];
    __shared__ float h0[256];
    __shared__ float h1[512];
    __shared__ float pr[100];
    int tid = threadIdx.x;

    if (tid < DDIM) x[tid] = x_in[tid];
    __syncthreads();

    if (tid < 256) {
        float acc = b0[tid];
        #pragma unroll
        for (int k = 0; k < DDIM; k++) acc = fmaf(x[k], W0[k * 256 + tid], acc);
        h0[tid] = leaky(acc);
    }
    __syncthreads();

    {
        float acc = b1[tid];
        #pragma unroll 8
        for (int k = 0; k < 256; k++) acc = fmaf(h0[k], W1[k * 512 + tid], acc);
        h1[tid] = leaky(acc);
    }
    __syncthreads();

    if (tid < 100) {
        float acc = b2[tid];
        #pragma unroll 8
        for (int k = 0; k < 512; k++) acc = fmaf(h1[k], W2[k * 100 + tid], acc);
        float v = leaky(acc);
        pr[tid] = v;
        g_proto[tid] = v;
    }
    __syncthreads();

    if (tid < SLATE) {
        float s = 0.0f;
        #pragma unroll
        for (int d = 0; d < DDIM; d++) { float v = pr[tid * DDIM + d]; s = fmaf(v, v, s); }
        g_pn2[tid] = s;
    }
}

// -------- kernel 2: score all docs, store keys, build MSB histogram --------
__global__ __launch_bounds__(512) void score_kernel(const float* __restrict__ docs, int N)
{
    __shared__ unsigned shist[SLATE * NBINS];   // 40 KB
    __shared__ float sp[100];
    __shared__ float spn[SLATE];
    int tid = threadIdx.x;

    for (int t = tid; t < SLATE * NBINS; t += blockDim.x) shist[t] = 0;
    if (tid < 100) sp[tid] = g_proto[tid];
    if (tid < SLATE) spn[tid] = g_pn2[tid];
    __syncthreads();

    const float4* d4 = (const float4*)docs;   // 20 floats = 5 x float4 per row
    for (int i = blockIdx.x * blockDim.x + tid; i < N; i += gridDim.x * blockDim.x) {
        size_t base = (size_t)i * 5;
        float4 v0 = d4[base + 0], v1 = d4[base + 1], v2 = d4[base + 2],
               v3 = d4[base + 3], v4 = d4[base + 4];
        float vv[20] = { v0.x, v0.y, v0.z, v0.w,  v1.x, v1.y, v1.z, v1.w,
                         v2.x, v2.y, v2.z, v2.w,  v3.x, v3.y, v3.z, v3.w,
                         v4.x, v4.y, v4.z, v4.w };
        float cn2 = 0.0f;
        #pragma unroll
        for (int k = 0; k < DDIM; k++) cn2 = fmaf(vv[k], vv[k], cn2);

        #pragma unroll
        for (int j = 0; j < SLATE; j++) {
            float dot = 0.0f;
            #pragma unroll
            for (int k = 0; k < DDIM; k++) dot = fmaf(sp[j * DDIM + k], vv[k], dot);
            float d2 = cn2 - 2.0f * dot + spn[j];
            unsigned key = fkey(d2);
            g_keys[(size_t)j * N + i] = key;
            unsigned bin = key >> 21;
            // warp-aggregated histogram: bulk bins would serialize shared atomics
            unsigned am = __activemask();
            unsigned m  = __match_any_sync(am, bin);
            int leader  = __ffs(m) - 1;
            if ((int)(threadIdx.x & 31) == leader)
                atomicAdd(&shist[j * NBINS + bin], (unsigned)__popc(m));
        }
    }
    __syncthreads();
    for (int t = tid; t < SLATE * NBINS; t += blockDim.x) {
        unsigned c = shist[t];
        if (c) atomicAdd(&g_hist[t], c);
    }
}

// -------- kernel 3: parallel per-row scan, find bin of K-th smallest --------
// One block per slate row. 1024 threads, 2 bins each. Warp-shuffle inclusive
// scan of pair-sums + cross-warp scan, then atomicMin over the first bin whose
// cumulative count reaches KSEL.
__global__ __launch_bounds__(1024) void scan_kernel() {
    __shared__ unsigned sbin[NBINS];
    __shared__ unsigned warpsum[32];
    __shared__ unsigned result;
    int r   = blockIdx.x;
    int tid = threadIdx.x;

    sbin[tid]        = g_hist[r * NBINS + tid];
    sbin[tid + 1024] = g_hist[r * NBINS + tid + 1024];
    if (tid == 0) result = 0xFFFFFFFFu;
    __syncthreads();

    unsigned b0 = sbin[2 * tid];
    unsigned b1 = sbin[2 * tid + 1];
    unsigned v  = b0 + b1;

    // inclusive scan of v within warp
    unsigned inc = v;
    #pragma unroll
    for (int d = 1; d < 32; d <<= 1) {
        unsigned t = __shfl_up_sync(0xFFFFFFFFu, inc, d);
        if ((tid & 31) >= d) inc += t;
    }
    if ((tid & 31) == 31) warpsum[tid >> 5] = inc;
    __syncthreads();

    // scan of 32 warp totals by warp 0
    if (tid < 32) {
        unsigned w = warpsum[tid];
        #pragma unroll
        for (int d = 1; d < 32; d <<= 1) {
            unsigned t = __shfl_up_sync(0xFFFFFFFFu, w, d);
            if (tid >= d) w += t;
        }
        warpsum[tid] = w;
    }
    __syncthreads();

    unsigned base = (tid >= 32) ? warpsum[(tid >> 5) - 1] : 0u;
    unsigned cum_after = base + inc;            // cumulative through bin 2t+1
    unsigned cum_mid   = cum_after - b1;        // cumulative through bin 2t
    unsigned cand = 0xFFFFFFFFu;
    if (cum_mid   >= KSEL) cand = 2u * tid;
    else if (cum_after >= KSEL) cand = 2u * tid + 1u;
    if (cand != 0xFFFFFFFFu) atomicMin(&result, cand);
    __syncthreads();

    if (tid == 0) {
        unsigned b = result;
        g_keyLimit[r] = (b >= NBINS - 1) ? 0xFFFFFFFFu : ((b + 1u) << 21);
    }
}

// -------- kernel 4: compact candidates below limit --------
__global__ __launch_bounds__(512) void collect_kernel(int N)
{
    __shared__ unsigned lim[SLATE];
    if (threadIdx.x < SLATE) lim[threadIdx.x] = g_keyLimit[threadIdx.x];
    __syncthreads();

    for (int i = blockIdx.x * blockDim.x + threadIdx.x; i < N;
         i += gridDim.x * blockDim.x) {
        #pragma unroll
        for (int j = 0; j < SLATE; j++) {
            unsigned key = g_keys[(size_t)j * N + i];
            if (key < lim[j]) {
                unsigned pos = atomicAdd(&g_candCount[j], 1u);
                if (pos < CAP)
                    g_cand[(size_t)j * CAP + pos] =
                        ((unsigned long long)key << 32) | (unsigned)i;
            }
        }
    }
}

// -------- kernel 5: exact rank among candidates, gather output --------
// Packed (key<<32)|idx compares exactly like jax top_k ordering:
// ascending d2, ties broken by lower index.
__global__ __launch_bounds__(1024) void select_kernel(
    const float* __restrict__ docs, float* __restrict__ out, int out_size)
{
    extern __shared__ unsigned long long sh[];
    int j = blockIdx.x;
    int n = (int)min(g_candCount[j], (unsigned)CAP);
    int nsh = n < SH_CAP ? n : SH_CAP;

    for (int t = threadIdx.x; t < nsh; t += blockDim.x)
        sh[t] = g_cand[(size_t)j * CAP + t];
    __syncthreads();

    for (int t = threadIdx.x; t < n; t += blockDim.x) {
        unsigned long long my = (t < nsh) ? sh[t] : g_cand[(size_t)j * CAP + t];
        int rank = 0;
        for (int s = 0; s < nsh; s++) rank += (sh[s] < my);
        for (int s = nsh; s < n; s++) rank += (g_cand[(size_t)j * CAP + s] < my);

        if (rank < KSEL) {
            unsigned di  = (unsigned)(my & 0xFFFFFFFFu);
            int orow     = j * KSEL + rank;
            if (out_size >= SLATE * KSEL * DDIM) {
                const float4* s4 = (const float4*)(docs + (size_t)di * DDIM);
                float4* o4 = (float4*)(out + (size_t)orow * DDIM);
                #pragma unroll
                for (int k = 0; k < 5; k++) o4[k] = s4[k];
                if (out_size >= SLATE * KSEL * DDIM + SLATE * KSEL)
                    out[SLATE * KSEL * DDIM + orow] = (float)di;
            } else {
                // indices-only output layout
                out[orow] = (float)di;
            }
        }
    }
}

extern "C" void kernel_launch(void* const* d_in, const int* in_sizes, int n_in,
                              void* d_out, int out_size)
{
    const float* state = (const float*)d_in[0];
    const float* docs  = (const float*)d_in[1];
    const float* W0    = (const float*)d_in[2];
    const float* b0    = (const float*)d_in[3];
    const float* W1    = (const float*)d_in[4];
    const float* b1    = (const float*)d_in[5];
    const float* W2    = (const float*)d_in[6];
    const float* b2    = (const float*)d_in[7];
    float* out = (float*)d_out;

    int N = in_sizes[1] / DDIM;
    if (N > MAXN) N = MAXN;

    const int threads = 512;
    int blocks = (N + threads * 4 - 1) / (threads * 4);
    if (blocks > 2048) blocks = 2048;
    if (blocks < 1) blocks = 1;

    init_kernel<<<1, 1024>>>();
    mlp_kernel<<<1, 512>>>(state, W0, b0, W1, b1, W2, b2);
    score_kernel<<<blocks, threads>>>(docs, N);
    scan_kernel<<<SLATE, 1024>>>();
    collect_kernel<<<blocks, threads>>>(N);
    select_kernel<<<SLATE, 1024, SH_CAP * sizeof(unsigned long long)>>>(docs, out, out_size);
}

// round 3
// speedup vs baseline: 2.1340x; 1.2865x over previous
#include <cuda_runtime.h>
#include <cstdint>

#define SLATE   5
#define DDIM    20
#define KSEL    100
#define MAXN    2000000
#define NBINS   2048
#define CAP     65536
#define SH_KEYS 8192
#define SV_CAP  512

// -------- device scratch (allocation-free module globals) --------
__device__ float          g_proto[128];
__device__ float          g_pn2[8];
__device__ unsigned short g_key16[(size_t)SLATE * MAXN];   // 20 MB
__device__ unsigned       g_hist[SLATE * NBINS];
__device__ unsigned       g_keyLimit[8];                   // 16-bit-space exclusive limit
__device__ unsigned       g_candCount[8];
__device__ unsigned       g_candIdx[(size_t)SLATE * CAP];
__device__ unsigned       g_candKey[(size_t)SLATE * CAP];
__device__ unsigned       g_done;

__device__ __forceinline__ float leaky(float x) { return x > 0.0f ? x : 0.01f * x; }

// ---- shared math helpers: MUST be used by both score and select so the
// ---- recomputed keys are bit-identical to pass-1 keys.
__device__ __forceinline__ void unpack20(const float4* d5, float* vv) {
    #pragma unroll
    for (int q = 0; q < 5; q++) {
        float4 v = d5[q];
        vv[4*q+0] = v.x; vv[4*q+1] = v.y; vv[4*q+2] = v.z; vv[4*q+3] = v.w;
    }
}
__device__ __forceinline__ float norm20(const float* vv) {
    float c = 0.0f;
    #pragma unroll
    for (int k = 0; k < DDIM; k++) c = fmaf(vv[k], vv[k], c);
    return c;
}
__device__ __forceinline__ float dot20(const float4* p, const float* vv) {
    float d = 0.0f;
    #pragma unroll
    for (int q = 0; q < 5; q++) {
        float4 w = p[q];
        d = fmaf(w.x, vv[4*q+0], d); d = fmaf(w.y, vv[4*q+1], d);
        d = fmaf(w.z, vv[4*q+2], d); d = fmaf(w.w, vv[4*q+3], d);
    }
    return d;
}
__device__ __forceinline__ unsigned key20(float cn2, float dot, float pn) {
    float d2 = fmaf(-2.0f, dot, cn2) + pn;
    d2 = fmaxf(d2, 0.0f);               // positive floats: raw bits are monotone
    return __float_as_uint(d2);
}

// ---- block-wide "first bin with inclusive cum >= r" over NB bins ----
template<int NB, int BD>
__device__ void find_bin(const unsigned* hist, unsigned r, unsigned* warpsum,
                         unsigned* s_res, unsigned* s_prefix)
{
    const int tid = threadIdx.x;
    constexpr int PB = NB / BD;
    unsigned local[PB];
    unsigned v = 0;
    #pragma unroll
    for (int p = 0; p < PB; p++) { local[p] = hist[tid * PB + p]; v += local[p]; }

    unsigned inc = v;
    #pragma unroll
    for (int d = 1; d < 32; d <<= 1) {
        unsigned t = __shfl_up_sync(0xFFFFFFFFu, inc, d);
        if ((tid & 31) >= d) inc += t;
    }
    if ((tid & 31) == 31) warpsum[tid >> 5] = inc;
    if (tid == 0) *s_res = 0xFFFFFFFFu;
    __syncthreads();

    if (tid < 32) {
        constexpr int NW = BD / 32;
        unsigned w = (tid < NW) ? warpsum[tid] : 0u;
        #pragma unroll
        for (int d = 1; d < 32; d <<= 1) {
            unsigned t = __shfl_up_sync(0xFFFFFFFFu, w, d);
            if (tid >= d) w += t;
        }
        warpsum[tid] = w;
    }
    __syncthreads();

    unsigned base   = (tid >= 32) ? warpsum[(tid >> 5) - 1] : 0u;
    unsigned before = base + inc - v;
    unsigned run = before;
    unsigned myBin = 0xFFFFFFFFu;
    #pragma unroll
    for (int p = 0; p < PB; p++) {
        run += local[p];
        if (myBin == 0xFFFFFFFFu && run >= r) myBin = (unsigned)(tid * PB + p);
    }
    if (myBin != 0xFFFFFFFFu) atomicMin(s_res, myBin);
    __syncthreads();

    unsigned winner = *s_res;
    if (winner != 0xFFFFFFFFu && winner / PB == (unsigned)tid) {
        unsigned pf = before;
        for (unsigned p = 0; p < winner % PB; p++) pf += local[p];
        *s_prefix = pf;
    }
    __syncthreads();
}

// -------- kernel 1: MLP + zero scratch --------
__global__ __launch_bounds__(1024) void mlp_kernel(
    const float* __restrict__ x_in,
    const float* __restrict__ W0, const float* __restrict__ b0,
    const float* __restrict__ W1, const float* __restrict__ b1,
    const float* __restrict__ W2, const float* __restrict__ b2)
{
    __shared__ float x[DDIM];
    __shared__ float h0[256];
    __shared__ float h1[512];
    __shared__ float p2[2 * 512];
    __shared__ float p3[8 * 100];
    __shared__ float pr[100];
    int tid = threadIdx.x;

    // zero global scratch (runs before score in stream order)
    for (int i = tid; i < SLATE * NBINS; i += 1024) g_hist[i] = 0;
    if (tid < 8) g_candCount[tid] = 0;

    if (tid < DDIM) x[tid] = x_in[tid];
    __syncthreads();

    if (tid < 256) {
        float acc = b0[tid];
        #pragma unroll
        for (int k = 0; k < DDIM; k++) acc = fmaf(x[k], W0[k * 256 + tid], acc);
        h0[tid] = leaky(acc);
    }
    __syncthreads();

    {   // layer 2: 512 outputs, k split 2 ways across 1024 threads
        int o = tid & 511, c = tid >> 9;
        float acc = 0.0f;
        int k0 = c * 128;
        #pragma unroll 8
        for (int k = k0; k < k0 + 128; k++) acc = fmaf(h0[k], W1[k * 512 + o], acc);
        p2[c * 512 + o] = acc;
    }
    __syncthreads();
    if (tid < 512) h1[tid] = leaky(b1[tid] + p2[tid] + p2[512 + tid]);
    __syncthreads();

    {   // layer 3: 100 outputs, k split 8 ways
        int o = tid & 127, c = tid >> 7;
        if (o < 100) {
            float acc = 0.0f;
            int k0 = c * 64;
            #pragma unroll 8
            for (int k = k0; k < k0 + 64; k++) acc = fmaf(h1[k], W2[k * 100 + o], acc);
            p3[c * 100 + o] = acc;
        }
    }
    __syncthreads();
    if (tid < 100) {
        float s = b2[tid];
        #pragma unroll
        for (int c = 0; c < 8; c++) s += p3[c * 100 + tid];   // fixed order: deterministic
        float v = leaky(s);
        pr[tid] = v;
        g_proto[tid] = v;
    }
    __syncthreads();
    if (tid < SLATE) {
        float s = 0.0f;
        #pragma unroll
        for (int d = 0; d < DDIM; d++) { float v = pr[tid * DDIM + d]; s = fmaf(v, v, s); }
        g_pn2[tid] = s;
    }
}

// -------- kernel 2: score all docs, 16-bit keys, histogram; last block scans --------
__global__ __launch_bounds__(512) void score_kernel(const float* __restrict__ docs, int N)
{
    __shared__ unsigned shist[SLATE * NBINS];   // 40 KB; row 0 reused by epilogue
    __shared__ float4   sp4[25];
    __shared__ float    spn[SLATE];
    __shared__ unsigned swarp[32];
    __shared__ unsigned sres, spre, slast;
    int tid = threadIdx.x;

    for (int t = tid; t < SLATE * NBINS; t += blockDim.x) shist[t] = 0;
    if (tid < 25) sp4[tid] = ((const float4*)g_proto)[tid];
    if (tid < SLATE) spn[tid] = g_pn2[tid];
    __syncthreads();

    const float4* d4 = (const float4*)docs;
    for (int i = blockIdx.x * blockDim.x + tid; i < N; i += gridDim.x * blockDim.x) {
        float4 dv[5];
        size_t base = (size_t)i * 5;
        #pragma unroll
        for (int q = 0; q < 5; q++) dv[q] = d4[base + q];
        float vv[20];
        unpack20(dv, vv);
        float cn2 = norm20(vv);

        #pragma unroll
        for (int j = 0; j < SLATE; j++) {
            float dot = dot20(&sp4[j * 5], vv);
            unsigned key = key20(cn2, dot, spn[j]);
            g_key16[(size_t)j * N + i] = (unsigned short)(key >> 16);
            unsigned hidx = j * NBINS + (key >> 21);
            unsigned am = __activemask();
            unsigned m  = __match_any_sync(am, hidx);
            if ((int)(threadIdx.x & 31) == (__ffs(m) - 1))
                atomicAdd(&shist[hidx], (unsigned)__popc(m));
        }
    }
    __syncthreads();
    for (int t = tid; t < SLATE * NBINS; t += blockDim.x) {
        unsigned c = shist[t];
        if (c) atomicAdd(&g_hist[t], c);
    }

    // ---- last-block epilogue: per-row scan for the K-th bin ----
    __threadfence();
    if (tid == 0) slast = (atomicAdd(&g_done, 1u) == gridDim.x - 1) ? 1u : 0u;
    __syncthreads();
    if (!slast) return;
    __threadfence();

    for (int r = 0; r < SLATE; r++) {
        for (int i = tid; i < NBINS; i += 512)
            shist[i] = __ldcg(&g_hist[r * NBINS + i]);
        __syncthreads();
        find_bin<NBINS, 512>(shist, KSEL, swarp, &sres, &spre);
        if (tid == 0) {
            unsigned b = sres;
            g_keyLimit[r] = (b >= NBINS - 1) ? 65536u : ((b + 1u) << 5);  // 16-bit space
        }
        __syncthreads();
    }
    if (tid == 0) g_done = 0;   // reset for graph replay
}

// -------- kernel 3: compact candidate indices below limit --------
__global__ __launch_bounds__(512) void collect_kernel(int N)
{
    __shared__ unsigned lim[SLATE];
    if (threadIdx.x < SLATE) lim[threadIdx.x] = g_keyLimit[threadIdx.x];
    __syncthreads();

    for (int i = blockIdx.x * blockDim.x + threadIdx.x; i < N;
         i += gridDim.x * blockDim.x) {
        #pragma unroll
        for (int j = 0; j < SLATE; j++) {
            unsigned k16 = (unsigned)g_key16[(size_t)j * N + i];
            if (k16 < lim[j]) {
                unsigned pos = atomicAdd(&g_candCount[j], 1u);
                if (pos < CAP) g_candIdx[(size_t)j * CAP + pos] = (unsigned)i;
            }
        }
    }
}

// -------- kernel 4: exact keys + radix select of 100th + rank survivors --------
__global__ __launch_bounds__(1024) void select_kernel(
    const float* __restrict__ docs, float* __restrict__ out, int out_size)
{
    __shared__ unsigned           skey[SH_KEYS];      // 32 KB
    __shared__ unsigned           hist[NBINS];        // 8 KB
    __shared__ float4             sp4[25];
    __shared__ float              spn[SLATE];
    __shared__ unsigned           swarp[32];
    __shared__ unsigned           sres, spre;
    __shared__ unsigned long long sv[SV_CAP];
    __shared__ unsigned           svCount;

    int j   = blockIdx.x;
    int tid = threadIdx.x;
    size_t cbase = (size_t)j * CAP;
    int n = (int)min(g_candCount[j], (unsigned)CAP);

    if (tid < 25) sp4[tid] = ((const float4*)g_proto)[tid];
    if (tid < SLATE) spn[tid] = g_pn2[tid];
    if (tid == 0) svCount = 0;
    __syncthreads();

    const float4* d4 = (const float4*)docs;

    // phase 0: exact keys (bit-identical to pass 1)
    for (int t = tid; t < n; t += 1024) {
        unsigned idx = g_candIdx[cbase + t];
        float4 dv[5];
        size_t b = (size_t)idx * 5;
        #pragma unroll
        for (int q = 0; q < 5; q++) dv[q] = d4[b + q];
        float vv[20];
        unpack20(dv, vv);
        float cn2 = norm20(vv);
        float dot = dot20(&sp4[j * 5], vv);
        unsigned key = key20(cn2, dot, spn[j]);
        g_candKey[cbase + t] = key;
        if (t < SH_KEYS) skey[t] = key;
    }
    __syncthreads();

    // pass A: bits 31..21
    for (int i = tid; i < NBINS; i += 1024) hist[i] = 0;
    __syncthreads();
    for (int t = tid; t < n; t += 1024) {
        unsigned k = (t < SH_KEYS) ? skey[t] : g_candKey[cbase + t];
        atomicAdd(&hist[k >> 21], 1u);
    }
    __syncthreads();
    find_bin<NBINS, 1024>(hist, KSEL, swarp, &sres, &spre);
    unsigned bA = sres, pfA = spre;
    unsigned rB = KSEL - pfA;
    __syncthreads();

    // pass B: bits 20..10 within bA
    for (int i = tid; i < NBINS; i += 1024) hist[i] = 0;
    __syncthreads();
    for (int t = tid; t < n; t += 1024) {
        unsigned k = (t < SH_KEYS) ? skey[t] : g_candKey[cbase + t];
        if ((k >> 21) == bA) atomicAdd(&hist[(k >> 10) & 0x7FFu], 1u);
    }
    __syncthreads();
    find_bin<NBINS, 1024>(hist, rB, swarp, &sres, &spre);
    unsigned bB = sres;
    unsigned rC = rB - spre;
    unsigned hi21 = (bA << 11) | bB;
    __syncthreads();

    // pass C: bits 9..0 within (bA,bB)
    for (int i = tid; i < 1024; i += 1024) hist[i] = 0;
    __syncthreads();
    for (int t = tid; t < n; t += 1024) {
        unsigned k = (t < SH_KEYS) ? skey[t] : g_candKey[cbase + t];
        if ((k >> 10) == hi21) atomicAdd(&hist[k & 0x3FFu], 1u);
    }
    __syncthreads();
    find_bin<1024, 1024>(hist, rC, swarp, &sres, &spre);
    unsigned Kstar = (hi21 << 10) | sres;
    __syncthreads();

    // survivors: key <= Kstar
    for (int t = tid; t < n; t += 1024) {
        unsigned k = (t < SH_KEYS) ? skey[t] : g_candKey[cbase + t];
        if (k <= Kstar) {
            unsigned pos = atomicAdd(&svCount, 1u);
            if (pos < SV_CAP)
                sv[pos] = ((unsigned long long)k << 32) | g_candIdx[cbase + t];
        }
    }
    __syncthreads();

    int S = (int)min(svCount, (unsigned)SV_CAP);
    for (int t = tid; t < S; t += 1024) {
        unsigned long long my = sv[t];
        int rank = 0;
        for (int s = 0; s < S; s++) rank += (sv[s] < my);
        if (rank < KSEL) {
            unsigned di = (unsigned)(my & 0xFFFFFFFFu);
            int orow = j * KSEL + rank;
            if (out_size >= SLATE * KSEL * DDIM) {
                const float4* s4 = (const float4*)(docs + (size_t)di * DDIM);
                float4* o4 = (float4*)(out + (size_t)orow * DDIM);
                #pragma unroll
                for (int q = 0; q < 5; q++) o4[q] = s4[q];
                if (out_size >= SLATE * KSEL * DDIM + SLATE * KSEL)
                    out[SLATE * KSEL * DDIM + orow] = (float)di;
            } else {
                out[orow] = (float)di;
            }
        }
    }
}

extern "C" void kernel_launch(void* const* d_in, const int* in_sizes, int n_in,
                              void* d_out, int out_size)
{
    const float* state = (const float*)d_in[0];
    const float* docs  = (const float*)d_in[1];
    const float* W0    = (const float*)d_in[2];
    const float* b0    = (const float*)d_in[3];
    const float* W1    = (const float*)d_in[4];
    const float* b1    = (const float*)d_in[5];
    const float* W2    = (const float*)d_in[6];
    const float* b2    = (const float*)d_in[7];
    float* out = (float*)d_out;

    int N = in_sizes[1] / DDIM;
    if (N > MAXN) N = MAXN;

    const int threads = 512;
    int blocks = (N + threads * 4 - 1) / (threads * 4);
    if (blocks > 2048) blocks = 2048;
    if (blocks < 1) blocks = 1;

    mlp_kernel<<<1, 1024>>>(state, W0, b0, W1, b1, W2, b2);
    score_kernel<<<blocks, threads>>>(docs, N);
    collect_kernel<<<blocks, threads>>>(N);
    select_kernel<<<SLATE, 1024>>>(docs, out, out_size);
}

// round 4
// speedup vs baseline: 2.5590x; 1.1992x over previous
#include <cuda_runtime.h>
#include <cstdint>

#define SLATE   5
#define DDIM    20
#define KSEL    100
#define NBINS   2048
#define CAP     131072
#define SH_CAND 12288
#define SV_CAP  512
#define STGT    128        // sample-count guarantee target (>= KSEL)

// -------- device scratch (allocation-free module globals) --------
__device__ float              g_proto[128];
__device__ float              g_pn2[8];
__device__ unsigned           g_hist[SLATE * NBINS];
__device__ unsigned           g_thresh[8];                  // exclusive 32-bit key limit
__device__ unsigned           g_candCount[8];
__device__ unsigned long long g_cand[(size_t)SLATE * CAP];  // 5 MB
__device__ unsigned           g_done;

__device__ __forceinline__ float leaky(float x) { return x > 0.0f ? x : 0.01f * x; }

// ---- shared math helpers: used by sample AND score so keys are bit-identical
__device__ __forceinline__ void unpack20(const float4* d5, float* vv) {
    #pragma unroll
    for (int q = 0; q < 5; q++) {
        float4 v = d5[q];
        vv[4*q+0] = v.x; vv[4*q+1] = v.y; vv[4*q+2] = v.z; vv[4*q+3] = v.w;
    }
}
__device__ __forceinline__ float norm20(const float* vv) {
    float c = 0.0f;
    #pragma unroll
    for (int k = 0; k < DDIM; k++) c = fmaf(vv[k], vv[k], c);
    return c;
}
__device__ __forceinline__ float dot20(const float4* p, const float* vv) {
    float d = 0.0f;
    #pragma unroll
    for (int q = 0; q < 5; q++) {
        float4 w = p[q];
        d = fmaf(w.x, vv[4*q+0], d); d = fmaf(w.y, vv[4*q+1], d);
        d = fmaf(w.z, vv[4*q+2], d); d = fmaf(w.w, vv[4*q+3], d);
    }
    return d;
}
__device__ __forceinline__ unsigned key20(float cn2, float dot, float pn) {
    float d2 = fmaf(-2.0f, dot, cn2) + pn;
    d2 = fmaxf(d2, 0.0f);               // positive floats: raw bits monotone
    return __float_as_uint(d2);
}

// ---- block-wide "first bin with inclusive cum >= r" over NB bins ----
template<int NB, int BD>
__device__ void find_bin(const unsigned* hist, unsigned r, unsigned* warpsum,
                         unsigned* s_res, unsigned* s_prefix)
{
    const int tid = threadIdx.x;
    constexpr int PB = NB / BD;
    unsigned local[PB];
    unsigned v = 0;
    #pragma unroll
    for (int p = 0; p < PB; p++) { local[p] = hist[tid * PB + p]; v += local[p]; }

    unsigned inc = v;
    #pragma unroll
    for (int d = 1; d < 32; d <<= 1) {
        unsigned t = __shfl_up_sync(0xFFFFFFFFu, inc, d);
        if ((tid & 31) >= d) inc += t;
    }
    if ((tid & 31) == 31) warpsum[tid >> 5] = inc;
    if (tid == 0) *s_res = 0xFFFFFFFFu;
    __syncthreads();

    if (tid < 32) {
        constexpr int NW = BD / 32;
        unsigned w = (tid < NW) ? warpsum[tid] : 0u;
        #pragma unroll
        for (int d = 1; d < 32; d <<= 1) {
            unsigned t = __shfl_up_sync(0xFFFFFFFFu, w, d);
            if (tid >= d) w += t;
        }
        warpsum[tid] = w;
    }
    __syncthreads();

    unsigned base   = (tid >= 32) ? warpsum[(tid >> 5) - 1] : 0u;
    unsigned before = base + inc - v;
    unsigned run = before;
    unsigned myBin = 0xFFFFFFFFu;
    #pragma unroll
    for (int p = 0; p < PB; p++) {
        run += local[p];
        if (myBin == 0xFFFFFFFFu && run >= r) myBin = (unsigned)(tid * PB + p);
    }
    if (myBin != 0xFFFFFFFFu) atomicMin(s_res, myBin);
    __syncthreads();

    unsigned winner = *s_res;
    if (winner != 0xFFFFFFFFu && winner / PB == (unsigned)tid) {
        unsigned pf = before;
        for (unsigned p = 0; p < winner % PB; p++) pf += local[p];
        *s_prefix = pf;
    }
    __syncthreads();
}

// -------- kernel 1: MLP + zero scratch --------
__global__ __launch_bounds__(1024) void mlp_kernel(
    const float* __restrict__ x_in,
    const float* __restrict__ W0, const float* __restrict__ b0,
    const float* __restrict__ W1, const float* __restrict__ b1,
    const float* __restrict__ W2, const float* __restrict__ b2)
{
    __shared__ float x[DDIM];
    __shared__ float h0[256];
    __shared__ float h1[512];
    __shared__ float p2[2 * 512];
    __shared__ float p3[8 * 100];
    __shared__ float pr[100];
    int tid = threadIdx.x;

    for (int i = tid; i < SLATE * NBINS; i += 1024) g_hist[i] = 0;
    if (tid < 8) g_candCount[tid] = 0;

    if (tid < DDIM) x[tid] = x_in[tid];
    __syncthreads();

    if (tid < 256) {
        float acc = b0[tid];
        #pragma unroll
        for (int k = 0; k < DDIM; k++) acc = fmaf(x[k], W0[k * 256 + tid], acc);
        h0[tid] = leaky(acc);
    }
    __syncthreads();

    {   // layer 2: 512 outputs, k split 2 ways
        int o = tid & 511, c = tid >> 9;
        float acc = 0.0f;
        int k0 = c * 128;
        #pragma unroll 8
        for (int k = k0; k < k0 + 128; k++) acc = fmaf(h0[k], W1[k * 512 + o], acc);
        p2[c * 512 + o] = acc;
    }
    __syncthreads();
    if (tid < 512) h1[tid] = leaky(b1[tid] + p2[tid] + p2[512 + tid]);
    __syncthreads();

    {   // layer 3: 100 outputs, k split 8 ways
        int o = tid & 127, c = tid >> 7;
        if (o < 100) {
            float acc = 0.0f;
            int k0 = c * 64;
            #pragma unroll 8
            for (int k = k0; k < k0 + 64; k++) acc = fmaf(h1[k], W2[k * 100 + o], acc);
            p3[c * 100 + o] = acc;
        }
    }
    __syncthreads();
    if (tid < 100) {
        float s = b2[tid];
        #pragma unroll
        for (int c = 0; c < 8; c++) s += p3[c * 100 + tid];  // fixed order
        float v = leaky(s);
        pr[tid] = v;
        g_proto[tid] = v;
    }
    __syncthreads();
    if (tid < SLATE) {
        float s = 0.0f;
        #pragma unroll
        for (int d = 0; d < DDIM; d++) { float v = pr[tid * DDIM + d]; s = fmaf(v, v, s); }
        g_pn2[tid] = s;
    }
}

// -------- kernel 2: sample histogram -> per-row conservative threshold --------
// Samples contiguous 256-doc chunks (1/16 of data). A threshold with >= STGT
// sampled docs below it has >= STGT real docs below it (sample is a subset),
// so >= KSEL candidates are guaranteed unconditionally.
__global__ __launch_bounds__(512) void sample_kernel(const float* __restrict__ docs,
                                                     int N, int S)
{
    __shared__ unsigned shist[SLATE * NBINS];   // 40 KB
    __shared__ float4   sp4[25];
    __shared__ float    spn[SLATE];
    __shared__ unsigned swarp[32];
    __shared__ unsigned sres, spre, slast;
    int tid = threadIdx.x;

    for (int t = tid; t < SLATE * NBINS; t += 512) shist[t] = 0;
    if (tid < 25) sp4[tid] = ((const float4*)g_proto)[tid];
    if (tid < SLATE) spn[tid] = g_pn2[tid];
    __syncthreads();

    const float4* d4 = (const float4*)docs;
    for (int s = blockIdx.x * blockDim.x + tid; s < S; s += gridDim.x * blockDim.x) {
        int i = ((s >> 8) << 12) + (s & 255);     // chunk c -> docs [4096c, 4096c+256)
        if (i >= N) continue;
        float4 dv[5];
        size_t base = (size_t)i * 5;
        #pragma unroll
        for (int q = 0; q < 5; q++) dv[q] = d4[base + q];
        float vv[20];
        unpack20(dv, vv);
        float cn2 = norm20(vv);
        #pragma unroll
        for (int j = 0; j < SLATE; j++) {
            float dot = dot20(&sp4[j * 5], vv);
            unsigned key = key20(cn2, dot, spn[j]);
            unsigned hidx = j * NBINS + (key >> 21);
            unsigned am = __activemask();
            unsigned m  = __match_any_sync(am, hidx);
            if ((int)(threadIdx.x & 31) == (__ffs(m) - 1))
                atomicAdd(&shist[hidx], (unsigned)__popc(m));
        }
    }
    __syncthreads();
    for (int t = tid; t < SLATE * NBINS; t += 512) {
        unsigned c = shist[t];
        if (c) atomicAdd(&g_hist[t], c);
    }

    __threadfence();
    if (tid == 0) slast = (atomicAdd(&g_done, 1u) == gridDim.x - 1) ? 1u : 0u;
    __syncthreads();
    if (!slast) return;
    __threadfence();

    for (int r = 0; r < SLATE; r++) {
        for (int i = tid; i < NBINS; i += 512)
            shist[i] = __ldcg(&g_hist[r * NBINS + i]);
        __syncthreads();
        find_bin<NBINS, 512>(shist, STGT, swarp, &sres, &spre);
        if (tid == 0) {
            unsigned b = sres;
            g_thresh[r] = (b >= NBINS - 1) ? 0xFFFFFFFFu : ((b + 1u) << 21);
        }
        __syncthreads();
    }
    if (tid == 0) g_done = 0;     // reset for graph replay
}

// -------- kernel 3: fused score + collect (no histogram, no key array) --------
__global__ __launch_bounds__(512) void score_kernel(const float* __restrict__ docs, int N)
{
    __shared__ float4   sp4[25];
    __shared__ float    spn[SLATE];
    __shared__ unsigned sT[SLATE];
    int tid = threadIdx.x;

    if (tid < 25) sp4[tid] = ((const float4*)g_proto)[tid];
    if (tid < SLATE) { spn[tid] = g_pn2[tid]; sT[tid] = g_thresh[tid]; }
    __syncthreads();

    const int lane = threadIdx.x & 31;
    const float4* d4 = (const float4*)docs;
    for (int i = blockIdx.x * blockDim.x + tid; i < N; i += gridDim.x * blockDim.x) {
        float4 dv[5];
        size_t base = (size_t)i * 5;
        #pragma unroll
        for (int q = 0; q < 5; q++) dv[q] = d4[base + q];
        float vv[20];
        unpack20(dv, vv);
        float cn2 = norm20(vv);

        #pragma unroll
        for (int j = 0; j < SLATE; j++) {
            float dot = dot20(&sp4[j * 5], vv);
            unsigned key = key20(cn2, dot, spn[j]);
            bool hit = key < sT[j];
            unsigned am = __activemask();
            unsigned m  = __ballot_sync(am, hit);
            if (m) {
                int ldr = __ffs(m) - 1;
                unsigned bpos = 0;
                if (lane == ldr) bpos = atomicAdd(&g_candCount[j], (unsigned)__popc(m));
                bpos = __shfl_sync(am, bpos, ldr);
                if (hit) {
                    unsigned pos = bpos + (unsigned)__popc(m & ((1u << lane) - 1u));
                    if (pos < CAP)
                        g_cand[(size_t)j * CAP + pos] =
                            ((unsigned long long)key << 32) | (unsigned)i;
                }
            }
        }
    }
}

// -------- kernel 4: radix select of exact 100th + rank survivors + gather ----
__global__ __launch_bounds__(1024) void select_kernel(
    const float* __restrict__ docs, float* __restrict__ out, int out_size)
{
    extern __shared__ unsigned long long sc[];      // SH_CAND packed candidates
    __shared__ unsigned           hist[NBINS];
    __shared__ unsigned           swarp[32];
    __shared__ unsigned           sres, spre;
    __shared__ unsigned long long sv[SV_CAP];
    __shared__ unsigned           svCount;

    int j   = blockIdx.x;
    int tid = threadIdx.x;
    size_t cbase = (size_t)j * CAP;
    int n = (int)min(g_candCount[j], (unsigned)CAP);
    int nsh = n < SH_CAND ? n : SH_CAND;

    if (tid == 0) svCount = 0;
    for (int t = tid; t < nsh; t += 1024) sc[t] = g_cand[cbase + t];
    __syncthreads();

    // pass A: bits 31..21
    for (int i = tid; i < NBINS; i += 1024) hist[i] = 0;
    __syncthreads();
    for (int t = tid; t < n; t += 1024) {
        unsigned k = (unsigned)(((t < nsh) ? sc[t] : g_cand[cbase + t]) >> 32);
        unsigned b = k >> 21;
        unsigned am = __activemask();
        unsigned m  = __match_any_sync(am, b);
        if ((int)(tid & 31) == (__ffs(m) - 1)) atomicAdd(&hist[b], (unsigned)__popc(m));
    }
    __syncthreads();
    find_bin<NBINS, 1024>(hist, KSEL, swarp, &sres, &spre);
    unsigned bA = sres;
    unsigned rB = KSEL - spre;
    __syncthreads();

    // pass B: bits 20..10 within bA
    for (int i = tid; i < NBINS; i += 1024) hist[i] = 0;
    __syncthreads();
    for (int t = tid; t < n; t += 1024) {
        unsigned k = (unsigned)(((t < nsh) ? sc[t] : g_cand[cbase + t]) >> 32);
        if ((k >> 21) == bA) atomicAdd(&hist[(k >> 10) & 0x7FFu], 1u);
    }
    __syncthreads();
    find_bin<NBINS, 1024>(hist, rB, swarp, &sres, &spre);
    unsigned bB = sres;
    unsigned rC = rB - spre;
    unsigned hi21 = (bA << 11) | bB;
    __syncthreads();

    // pass C: bits 9..0 within (bA,bB)
    if (tid < 1024) hist[tid] = 0;
    __syncthreads();
    for (int t = tid; t < n; t += 1024) {
        unsigned k = (unsigned)(((t < nsh) ? sc[t] : g_cand[cbase + t]) >> 32);
        if ((k >> 10) == hi21) atomicAdd(&hist[k & 0x3FFu], 1u);
    }
    __syncthreads();
    find_bin<1024, 1024>(hist, rC, swarp, &sres, &spre);
    unsigned Kstar = (hi21 << 10) | sres;
    __syncthreads();

    // survivors: key <= Kstar (ties resolved by packed 64-bit rank)
    for (int t = tid; t < n; t += 1024) {
        unsigned long long pk = (t < nsh) ? sc[t] : g_cand[cbase + t];
        if ((unsigned)(pk >> 32) <= Kstar) {
            unsigned pos = atomicAdd(&svCount, 1u);
            if (pos < SV_CAP) sv[pos] = pk;
        }
    }
    __syncthreads();

    int S = (int)min(svCount, (unsigned)SV_CAP);
    for (int t = tid; t < S; t += 1024) {
        unsigned long long my = sv[t];
        int rank = 0;
        for (int s = 0; s < S; s++) rank += (sv[s] < my);
        if (rank < KSEL) {
            unsigned di = (unsigned)(my & 0xFFFFFFFFu);
            int orow = j * KSEL + rank;
            if (out_size >= SLATE * KSEL * DDIM) {
                const float4* s4 = (const float4*)(docs + (size_t)di * DDIM);
                float4* o4 = (float4*)(out + (size_t)orow * DDIM);
                #pragma unroll
                for (int q = 0; q < 5; q++) o4[q] = s4[q];
                if (out_size >= SLATE * KSEL * DDIM + SLATE * KSEL)
                    out[SLATE * KSEL * DDIM + orow] = (float)di;
            } else {
                out[orow] = (float)di;
            }
        }
    }
}

extern "C" void kernel_launch(void* const* d_in, const int* in_sizes, int n_in,
                              void* d_out, int out_size)
{
    const float* state = (const float*)d_in[0];
    const float* docs  = (const float*)d_in[1];
    const float* W0    = (const float*)d_in[2];
    const float* b0    = (const float*)d_in[3];
    const float* W1    = (const float*)d_in[4];
    const float* b1    = (const float*)d_in[5];
    const float* W2    = (const float*)d_in[6];
    const float* b2    = (const float*)d_in[7];
    float* out = (float*)d_out;

    int N = in_sizes[1] / DDIM;
    int S = N >> 4;               // 1/16 sample
    if (S < 1) S = N;

    const int threads = 512;
    int blocks = (N + threads * 4 - 1) / (threads * 4);
    if (blocks > 2048) blocks = 2048;
    if (blocks < 1) blocks = 1;

    cudaFuncSetAttribute(select_kernel,
        cudaFuncAttributeMaxDynamicSharedMemorySize, SH_CAND * sizeof(unsigned long long));

    mlp_kernel<<<1, 1024>>>(state, W0, b0, W1, b1, W2, b2);
    sample_kernel<<<64, 512>>>(docs, N, S);
    score_kernel<<<blocks, threads>>>(docs, N);
    select_kernel<<<SLATE, 1024, SH_CAND * sizeof(unsigned long long)>>>(docs, out, out_size);
}